// round 16
// baseline (speedup 1.0000x reference)
#include <cuda_runtime.h>
#include <cuda_bf16.h>
#include <cstdint>

#define KS   5
#define K2   25
#define C1   32
#define C2   64
#define NG   64
#define NMAX 20000
#define EMAX 320000
#define KTOT 800
#define ZB   1024   // zero/prep blocks fused into edge1 grid

// ---------------- scratch (device globals; .bss-zeroed at load) ----------------
__device__ float        g_T[NMAX * K2];       // zeroed at tail of k_gemm_mma each call
__device__ float        g_deg[NMAX];          // idem
__device__ float        g_dinv[NMAX];
__device__ unsigned int g_h1b[NMAX * 16];     // h1 bf16x2 packed [N][16]
__device__ unsigned int g_Sb[NMAX * 400];     // S accum (32MB); zeroed by edge1's ZB blocks
__device__ uint2        g_W2f[56 * 8 * 32];   // B fragments; built by edge1's first 56 blocks
__device__ float        g_pool[NG * C2];      // zeroed at tail of k_mlp each call
__device__ uint4        g_rec[EMAX];          // {src|wi0<<20, dst, bw01 bf16x2, bw23 bf16x2}

// ---------------- helpers ----------------
__device__ __forceinline__ uint32_t smem_u32(const void* p) {
    uint32_t a;
    asm("{ .reg .u64 t; cvta.to.shared.u64 t, %1; cvt.u32.u64 %0, t; }" : "=r"(a) : "l"(p));
    return a;
}
__device__ __forceinline__ void red_bf162(unsigned int* addr, unsigned int v) {
    asm volatile("red.global.add.noftz.bf16x2 [%0], %1;" :: "l"(addr), "r"(v) : "memory");
}
__device__ __forceinline__ void red_f32(float* addr, float v) {
    asm volatile("red.global.add.f32 [%0], %1;" :: "l"(addr), "f"(v) : "memory");
}
__device__ __forceinline__ void ldmatrix_x4(uint32_t& a0, uint32_t& a1, uint32_t& a2,
                                            uint32_t& a3, uint32_t addr) {
    asm volatile("ldmatrix.sync.aligned.m8n8.x4.shared.b16 {%0,%1,%2,%3}, [%4];"
                 : "=r"(a0), "=r"(a1), "=r"(a2), "=r"(a3) : "r"(addr));
}
__device__ __forceinline__ void mma_bf16(float* c, uint32_t a0, uint32_t a1, uint32_t a2,
                                         uint32_t a3, uint32_t b0, uint32_t b1) {
    asm volatile(
        "mma.sync.aligned.m16n8k16.row.col.f32.bf16.bf16.f32 "
        "{%0,%1,%2,%3}, {%4,%5,%6,%7}, {%8,%9}, {%0,%1,%2,%3};"
        : "+f"(c[0]), "+f"(c[1]), "+f"(c[2]), "+f"(c[3])
        : "r"(a0), "r"(a1), "r"(a2), "r"(a3), "r"(b0), "r"(b1));
}

// ---------------- basis (wi0 form: indices are wi0, +1, +5, +6) ----------------
__device__ __forceinline__ void basis2w(float a0, float a1, int& wi0, float* bw) {
    float v0 = a0 * (KS - 1), v1 = a1 * (KS - 1);
    int k0 = (int)floorf(v0); k0 = min(max(k0, 0), KS - 2);
    int k1 = (int)floorf(v1); k1 = min(max(k1, 0), KS - 2);
    float f0 = v0 - (float)k0, f1 = v1 - (float)k1;
    float g0 = 1.f - f0, g1 = 1.f - f1;
    wi0 = k0 + KS * k1;
    bw[0] = g0 * g1;
    bw[1] = f0 * g1;
    bw[2] = g0 * f1;
    bw[3] = f0 * f1;
}

// ---------------- edge pass 1 + fused S-zero + W2f prep ----------------
__global__ void k_edge1(const float* __restrict__ x, const float* __restrict__ ea,
                        const int* __restrict__ src, const int* __restrict__ dst,
                        const float* __restrict__ W2, const float* __restrict__ root2,
                        int E, int N) {
    if (blockIdx.x < ZB) {
        if (blockIdx.x < 56) {
            int t = blockIdx.x * 256 + threadIdx.x;
            int lane = t & 31, ng = (t >> 5) & 7, sg = t >> 8;
            int gid = lane >> 2, tig = lane & 3;
            int n = ng * 8 + gid;
            int k = sg * 16 + tig * 2;
            float f0 = 0.f, f1 = 0.f, f2 = 0.f, f3 = 0.f;
            if (sg < 50) {
                f0 = W2[k * C2 + n];       f1 = W2[(k + 1) * C2 + n];
                f2 = W2[(k + 8) * C2 + n]; f3 = W2[(k + 9) * C2 + n];
            } else if (sg >= 52 && sg < 54) {
                int kr = k - 832;
                f0 = root2[kr * C2 + n];       f1 = root2[(kr + 1) * C2 + n];
                f2 = root2[(kr + 8) * C2 + n]; f3 = root2[(kr + 9) * C2 + n];
            }
            __nv_bfloat162 lo = __float22bfloat162_rn(make_float2(f0, f1));
            __nv_bfloat162 hi = __float22bfloat162_rn(make_float2(f2, f3));
            g_W2f[t] = make_uint2(*(uint32_t*)&lo, *(uint32_t*)&hi);
        }
        long total4 = (long)N * 100;                   // uint4 count
        long per = (total4 + ZB - 1) / ZB;
        long base = (long)blockIdx.x * per;
        long end = min(base + per, total4);
        uint4* S4 = (uint4*)g_Sb;
        uint4 z4 = make_uint4(0u, 0u, 0u, 0u);
        for (long i = base + threadIdx.x; i < end; i += blockDim.x) S4[i] = z4;
        return;
    }
    int e = (blockIdx.x - ZB) * blockDim.x + threadIdx.x;
    if (e >= E) return;
    int wi0; float bw[4];
    float2 eav = ((const float2*)ea)[e];
    basis2w(eav.x, eav.y, wi0, bw);
    int s = src[e];
    float xs = x[s];
    int d = dst[e];
    float* Tp = g_T + d * K2 + wi0;
    atomicAdd(Tp,     bw[0] * xs);
    atomicAdd(Tp + 1, bw[1] * xs);
    atomicAdd(Tp + 5, bw[2] * xs);
    atomicAdd(Tp + 6, bw[3] * xs);
    atomicAdd(g_deg + d, 1.f);
    __nv_bfloat162 c01 = __float22bfloat162_rn(make_float2(bw[0], bw[1]));
    __nv_bfloat162 c23 = __float22bfloat162_rn(make_float2(bw[2], bw[3]));
    g_rec[e] = make_uint4((uint32_t)s | ((uint32_t)wi0 << 20), (uint32_t)d,
                          *(uint32_t*)&c01, *(uint32_t*)&c23);
}

// ---------------- layer-1 node update (per-thread form, atomic-free) ----------------
__global__ void k_h1(const float* __restrict__ x, const float* __restrict__ W1,
                     const float* __restrict__ root1, const float* __restrict__ b1, int N) {
    int t = blockIdx.x * blockDim.x + threadIdx.x;
    if (t >= N * 16) return;
    int n = t >> 4, c2 = t & 15;
    const float* Tp = g_T + n * K2;
    float a0 = 0.f, a1 = 0.f;
#pragma unroll
    for (int w = 0; w < K2; w++) {
        float tv = Tp[w];
        a0 += tv * W1[w * C1 + 2 * c2];
        a1 += tv * W1[w * C1 + 2 * c2 + 1];
    }
    float dinv = 1.f / fmaxf(g_deg[n], 1.f);
    float xn = x[n];
    float h0 = fmaxf(a0 * dinv + xn * root1[2 * c2]     + b1[2 * c2],     0.f);
    float h1 = fmaxf(a1 * dinv + xn * root1[2 * c2 + 1] + b1[2 * c2 + 1], 0.f);
    __nv_bfloat162 hb = __float22bfloat162_rn(make_float2(h0, h1));
    g_h1b[t] = *(unsigned int*)&hb;
    if (c2 == 0) g_dinv[n] = dinv;
}

// ---------------- edge pass 2: 16 lanes/edge, 16B record + h1 gather ----------------
__global__ void k_edge2(int E) {
    int gt = blockIdx.x * blockDim.x + threadIdx.x;
    int lane = gt & 31;
    int warp = gt >> 5;
    int e = warp * 2 + (lane >> 4);
    int hl = lane & 15;
    if (e >= E) return;
    uint4 r = g_rec[e];
    int s   = (int)(r.x & 0xFFFFFu);
    int wi0 = (int)(r.x >> 20);
    int d   = (int)r.y;
    float2 bw01 = __bfloat1622float2(*(__nv_bfloat162*)&r.z);
    float2 bw23 = __bfloat1622float2(*(__nv_bfloat162*)&r.w);
    float2 h = __bfloat1622float2(*(__nv_bfloat162*)&g_h1b[s * 16 + hl]);
    unsigned int* base = g_Sb + d * 400 + wi0 * 16 + hl;
    {
        __nv_bfloat162 v = __float22bfloat162_rn(make_float2(bw01.x * h.x, bw01.x * h.y));
        red_bf162(base, *(unsigned int*)&v);
    }
    {
        __nv_bfloat162 v = __float22bfloat162_rn(make_float2(bw01.y * h.x, bw01.y * h.y));
        red_bf162(base + 16, *(unsigned int*)&v);
    }
    {
        __nv_bfloat162 v = __float22bfloat162_rn(make_float2(bw23.x * h.x, bw23.x * h.y));
        red_bf162(base + 80, *(unsigned int*)&v);
    }
    {
        __nv_bfloat162 v = __float22bfloat162_rn(make_float2(bw23.y * h.x, bw23.y * h.y));
        red_bf162(base + 96, *(unsigned int*)&v);
    }
}

// ---------------- fused GEMM (HMMA), M=64 tile for occupancy + epilogue + tail-zero ----------------
// 256 thr / 8 warps; warp w: rows 16*(w&3) .. +16, col-group (w>>2) (32 cols)
__global__ void __launch_bounds__(256) k_gemm_mma(const float* __restrict__ b2,
                                                  const int* __restrict__ batch, int N) {
    __shared__ __align__(16) uint8_t smA[8192];
    int tid = threadIdx.x;
    int warp = tid >> 5, lane = tid & 31;
    int wrow = warp & 3, wcol = warp >> 2;      // row-quad, col-half
    int gid = lane >> 2, tig = lane & 3;
    int rowBase = blockIdx.x * 64;
    uint32_t smA_b = smem_u32(smA);

    int rowA[2], chA[2], stoff[2];
    bool inb[2];
#pragma unroll
    for (int j = 0; j < 2; j++) {
        int c = tid + 256 * j;                  // 0..511
        rowA[j] = c >> 3; chA[j] = c & 7;       // 64 rows x 8 chunks of 16B
        stoff[j] = rowA[j] * 128 + ((chA[j] ^ (rowA[j] & 7)) << 4);
        inb[j] = (rowBase + rowA[j]) < N;
    }

    float acc[4][4];
#pragma unroll
    for (int g = 0; g < 4; g++)
#pragma unroll
        for (int j = 0; j < 4; j++) acc[g][j] = 0.f;

    int r0 = rowBase + wrow * 16 + gid;
    int r1 = r0 + 8;

    uint4 v[2];
#pragma unroll
    for (int j = 0; j < 2; j++) {
        v[j] = make_uint4(0u, 0u, 0u, 0u);
        if (inb[j])
            v[j] = *(const uint4*)(g_Sb + (rowBase + rowA[j]) * 400 + chA[j] * 4);
    }

    for (int c0 = 0; c0 < 14; c0++) {
#pragma unroll
        for (int j = 0; j < 2; j++) *(uint4*)(smA + stoff[j]) = v[j];
        __syncthreads();
        if (c0 < 13) {
            int cn = c0 + 1;
#pragma unroll
            for (int j = 0; j < 2; j++) {
                v[j] = make_uint4(0u, 0u, 0u, 0u);
                if (inb[j]) {
                    if (cn < 13) {
                        int off = cn * 32 + chA[j] * 4;
                        if (off < 400)
                            v[j] = *(const uint4*)(g_Sb + (rowBase + rowA[j]) * 400 + off);
                    } else if (chA[j] < 4) {
                        v[j] = *(const uint4*)(g_h1b + (rowBase + rowA[j]) * 16 + chA[j] * 4);
                    }
                }
            }
        }
#pragma unroll
        for (int ks = 0; ks < 4; ks++) {
            int mrow = wrow * 16 + (lane & 15);
            uint32_t addr = smA_b + mrow * 128 + (((ks * 2 + (lane >> 4)) ^ (mrow & 7)) << 4);
            uint32_t a0, a1, a2, a3;
            ldmatrix_x4(a0, a1, a2, a3, addr);
            int sg = c0 * 4 + ks;
            const uint2* bf = g_W2f + (sg << 8) + (wcol << 7) + lane;
#pragma unroll
            for (int ng = 0; ng < 4; ng++) {
                uint2 b = bf[ng << 5];
                mma_bf16(acc[ng], a0, a1, a2, a3, b.x, b.y);
            }
        }
        if (c0 == 12) {
            float di0 = (r0 < N) ? g_dinv[r0] : 0.f;
            float di1 = (r1 < N) ? g_dinv[r1] : 0.f;
#pragma unroll
            for (int ng = 0; ng < 4; ng++) {
                acc[ng][0] *= di0; acc[ng][1] *= di0;
                acc[ng][2] *= di1; acc[ng][3] *= di1;
            }
        }
        __syncthreads();
    }

    int bt0 = (r0 < N) ? batch[r0] : -1;
    int bt1 = (r1 < N) ? batch[r1] : -1;
#pragma unroll
    for (int ng = 0; ng < 4; ng++) {
        int col = wcol * 32 + ng * 8 + tig * 2;
        float2 bb = *(const float2*)(b2 + col);
        if (bt0 >= 0) {
            red_f32(g_pool + bt0 * C2 + col,     fmaxf(acc[ng][0] + bb.x, 0.f));
            red_f32(g_pool + bt0 * C2 + col + 1, fmaxf(acc[ng][1] + bb.y, 0.f));
        }
        if (bt1 >= 0) {
            red_f32(g_pool + bt1 * C2 + col,     fmaxf(acc[ng][2] + bb.x, 0.f));
            red_f32(g_pool + bt1 * C2 + col + 1, fmaxf(acc[ng][3] + bb.y, 0.f));
        }
    }

    // tail: zero T/deg for the next call (already consumed by h1 this call)
    int ztid = blockIdx.x * 256 + tid;
    int zstride = gridDim.x * 256;
    for (int i = ztid; i < N * K2; i += zstride) g_T[i] = 0.f;
    for (int i = ztid; i < N; i += zstride) g_deg[i] = 0.f;
}

// ---------------- head MLP + log_softmax + pool tail-zero ----------------
__global__ void k_mlp(const float* __restrict__ Wf1, const float* __restrict__ bf1,
                      const float* __restrict__ Wf2, const float* __restrict__ bf2,
                      const int* __restrict__ batch, int N,
                      float* __restrict__ out) {
    int b = blockIdx.x;
    int j = threadIdx.x;
    __shared__ float gs[C2];
    __shared__ float ts[128];
    __shared__ float lg[10];
    __shared__ float s_cinv;
    if (j == 0) {
        int lo = 0, hi = N;
        while (lo < hi) { int m = (lo + hi) >> 1; if (batch[m] < b) lo = m + 1; else hi = m; }
        int lo2 = lo; hi = N;
        while (lo2 < hi) { int m = (lo2 + hi) >> 1; if (batch[m] < b + 1) lo2 = m + 1; else hi = m; }
        s_cinv = 1.f / fmaxf((float)(lo2 - lo), 1.f);
    }
    __syncthreads();
    if (j < C2) gs[j] = g_pool[b * C2 + j] * s_cinv;
    __syncthreads();
    if (j < C2) g_pool[b * C2 + j] = 0.f;   // tail-zero for next call
    float t = bf1[j];
#pragma unroll
    for (int k = 0; k < C2; k++) t += gs[k] * Wf1[k * 128 + j];
    ts[j] = fmaxf(t, 0.f);
    __syncthreads();
    if (j < 10) {
        float a = bf2[j];
#pragma unroll
        for (int q = 0; q < 128; q++) a += ts[q] * Wf2[q * 10 + j];
        lg[j] = a;
    }
    __syncthreads();
    if (j == 0) {
        float m = lg[0];
#pragma unroll
        for (int q = 1; q < 10; q++) m = fmaxf(m, lg[q]);
        float s = 0.f;
#pragma unroll
        for (int q = 0; q < 10; q++) s += expf(lg[q] - m);
        float l = logf(s) + m;
#pragma unroll
        for (int q = 0; q < 10; q++) out[b * 10 + q] = lg[q] - l;
    }
}

// ---------------- launch ----------------
extern "C" void kernel_launch(void* const* d_in, const int* in_sizes, int n_in,
                              void* d_out, int out_size) {
    const float* x     = (const float*)d_in[0];
    const float* ea    = (const float*)d_in[1];
    const float* W1    = (const float*)d_in[2];
    const float* root1 = (const float*)d_in[3];
    const float* b1    = (const float*)d_in[4];
    const float* W2    = (const float*)d_in[5];
    const float* root2 = (const float*)d_in[6];
    const float* b2    = (const float*)d_in[7];
    const float* Wf1   = (const float*)d_in[8];
    const float* bf1   = (const float*)d_in[9];
    const float* Wf2   = (const float*)d_in[10];
    const float* bf2   = (const float*)d_in[11];
    const int*   ei    = (const int*)d_in[12];
    const int*   batch = (const int*)d_in[13];

    int N = in_sizes[0];
    int E = in_sizes[1] / 2;
    const int* src = ei;
    const int* dst = ei + E;
    float* out = (float*)d_out;

    k_edge1<<<ZB + (E + 255) / 256, 256>>>(x, ea, src, dst, W2, root2, E, N);
    k_h1<<<(N * 16 + 255) / 256, 256>>>(x, W1, root1, b1, N);
    k_edge2<<<(E * 16 + 255) / 256, 256>>>(E);
    k_gemm_mma<<<(N + 63) / 64, 256>>>(b2, batch, N);
    k_mlp<<<NG, 128>>>(Wf1, bf1, Wf2, bf2, batch, N, out);
}

// round 17
// speedup vs baseline: 1.0878x; 1.0878x over previous
#include <cuda_runtime.h>
#include <cuda_bf16.h>
#include <cstdint>

#define KS   5
#define K2   25
#define C1   32
#define C2   64
#define NG   64
#define NMAX 20000
#define EMAX 320000
#define KTOT 800
#define ZB   1024   // zero/prep blocks fused into edge1 grid

// ---------------- scratch (device globals; .bss-zeroed at load) ----------------
__device__ float        g_T[NMAX * K2];       // zeroed at tail of k_gemm_mma each call
__device__ float        g_deg[NMAX];          // idem
__device__ float        g_dinv[NMAX];
__device__ unsigned int g_h1b[NMAX * 16];     // h1 bf16x2 packed [N][16]
__device__ unsigned int g_Sb[NMAX * 400];     // S accum (32MB); zeroed by edge1's ZB blocks
__device__ uint2        g_W2f[56 * 8 * 32];   // B fragments; built by edge1's first 56 blocks
__device__ float        g_pool[NG * C2];      // zeroed at tail of k_mlp each call
__device__ uint4        g_rec[EMAX];          // {src|wi0<<20, dst, bw01 bf16x2, bw23 bf16x2}

// ---------------- helpers ----------------
__device__ __forceinline__ uint32_t smem_u32(const void* p) {
    uint32_t a;
    asm("{ .reg .u64 t; cvta.to.shared.u64 t, %1; cvt.u32.u64 %0, t; }" : "=r"(a) : "l"(p));
    return a;
}
__device__ __forceinline__ void red_bf162(unsigned int* addr, unsigned int v) {
    asm volatile("red.global.add.noftz.bf16x2 [%0], %1;" :: "l"(addr), "r"(v) : "memory");
}
__device__ __forceinline__ void red_f32(float* addr, float v) {
    asm volatile("red.global.add.f32 [%0], %1;" :: "l"(addr), "f"(v) : "memory");
}
__device__ __forceinline__ void ldmatrix_x4(uint32_t& a0, uint32_t& a1, uint32_t& a2,
                                            uint32_t& a3, uint32_t addr) {
    asm volatile("ldmatrix.sync.aligned.m8n8.x4.shared.b16 {%0,%1,%2,%3}, [%4];"
                 : "=r"(a0), "=r"(a1), "=r"(a2), "=r"(a3) : "r"(addr));
}
__device__ __forceinline__ void mma_bf16(float* c, uint32_t a0, uint32_t a1, uint32_t a2,
                                         uint32_t a3, uint32_t b0, uint32_t b1) {
    asm volatile(
        "mma.sync.aligned.m16n8k16.row.col.f32.bf16.bf16.f32 "
        "{%0,%1,%2,%3}, {%4,%5,%6,%7}, {%8,%9}, {%0,%1,%2,%3};"
        : "+f"(c[0]), "+f"(c[1]), "+f"(c[2]), "+f"(c[3])
        : "r"(a0), "r"(a1), "r"(a2), "r"(a3), "r"(b0), "r"(b1));
}
__device__ __forceinline__ void cp_async16(uint32_t smem, const void* gmem, bool pred) {
    int sz = pred ? 16 : 0;   // src-size 0 => 16B zero-fill
    asm volatile("cp.async.ca.shared.global [%0], [%1], 16, %2;"
                 :: "r"(smem), "l"(gmem), "r"(sz));
}
#define CP_COMMIT() asm volatile("cp.async.commit_group;" ::: "memory")
#define CP_WAIT(n)  asm volatile("cp.async.wait_group %0;" :: "n"(n) : "memory")

// ---------------- basis (wi0 form: indices are wi0, +1, +5, +6) ----------------
__device__ __forceinline__ void basis2w(float a0, float a1, int& wi0, float* bw) {
    float v0 = a0 * (KS - 1), v1 = a1 * (KS - 1);
    int k0 = (int)floorf(v0); k0 = min(max(k0, 0), KS - 2);
    int k1 = (int)floorf(v1); k1 = min(max(k1, 0), KS - 2);
    float f0 = v0 - (float)k0, f1 = v1 - (float)k1;
    float g0 = 1.f - f0, g1 = 1.f - f1;
    wi0 = k0 + KS * k1;
    bw[0] = g0 * g1;
    bw[1] = f0 * g1;
    bw[2] = g0 * f1;
    bw[3] = f0 * f1;
}

// ---------------- edge pass 1 + fused S-zero + W2f prep ----------------
__global__ void k_edge1(const float* __restrict__ x, const float* __restrict__ ea,
                        const int* __restrict__ src, const int* __restrict__ dst,
                        const float* __restrict__ W2, const float* __restrict__ root2,
                        int E, int N) {
    if (blockIdx.x < ZB) {
        if (blockIdx.x < 56) {
            int t = blockIdx.x * 256 + threadIdx.x;
            int lane = t & 31, ng = (t >> 5) & 7, sg = t >> 8;
            int gid = lane >> 2, tig = lane & 3;
            int n = ng * 8 + gid;
            int k = sg * 16 + tig * 2;
            float f0 = 0.f, f1 = 0.f, f2 = 0.f, f3 = 0.f;
            if (sg < 50) {
                f0 = W2[k * C2 + n];       f1 = W2[(k + 1) * C2 + n];
                f2 = W2[(k + 8) * C2 + n]; f3 = W2[(k + 9) * C2 + n];
            } else if (sg >= 52 && sg < 54) {
                int kr = k - 832;
                f0 = root2[kr * C2 + n];       f1 = root2[(kr + 1) * C2 + n];
                f2 = root2[(kr + 8) * C2 + n]; f3 = root2[(kr + 9) * C2 + n];
            }
            __nv_bfloat162 lo = __float22bfloat162_rn(make_float2(f0, f1));
            __nv_bfloat162 hi = __float22bfloat162_rn(make_float2(f2, f3));
            g_W2f[t] = make_uint2(*(uint32_t*)&lo, *(uint32_t*)&hi);
        }
        long total4 = (long)N * 100;                   // uint4 count
        long per = (total4 + ZB - 1) / ZB;
        long base = (long)blockIdx.x * per;
        long end = min(base + per, total4);
        uint4* S4 = (uint4*)g_Sb;
        uint4 z4 = make_uint4(0u, 0u, 0u, 0u);
        for (long i = base + threadIdx.x; i < end; i += blockDim.x) S4[i] = z4;
        return;
    }
    int e = (blockIdx.x - ZB) * blockDim.x + threadIdx.x;
    if (e >= E) return;
    int wi0; float bw[4];
    float2 eav = ((const float2*)ea)[e];
    basis2w(eav.x, eav.y, wi0, bw);
    int s = src[e];
    float xs = x[s];
    int d = dst[e];
    float* Tp = g_T + d * K2 + wi0;
    atomicAdd(Tp,     bw[0] * xs);
    atomicAdd(Tp + 1, bw[1] * xs);
    atomicAdd(Tp + 5, bw[2] * xs);
    atomicAdd(Tp + 6, bw[3] * xs);
    atomicAdd(g_deg + d, 1.f);
    __nv_bfloat162 c01 = __float22bfloat162_rn(make_float2(bw[0], bw[1]));
    __nv_bfloat162 c23 = __float22bfloat162_rn(make_float2(bw[2], bw[3]));
    g_rec[e] = make_uint4((uint32_t)s | ((uint32_t)wi0 << 20), (uint32_t)d,
                          *(uint32_t*)&c01, *(uint32_t*)&c23);
}

// ---------------- layer-1 node update (per-thread form, atomic-free) ----------------
__global__ void k_h1(const float* __restrict__ x, const float* __restrict__ W1,
                     const float* __restrict__ root1, const float* __restrict__ b1, int N) {
    int t = blockIdx.x * blockDim.x + threadIdx.x;
    if (t >= N * 16) return;
    int n = t >> 4, c2 = t & 15;
    const float* Tp = g_T + n * K2;
    float a0 = 0.f, a1 = 0.f;
#pragma unroll
    for (int w = 0; w < K2; w++) {
        float tv = Tp[w];
        a0 += tv * W1[w * C1 + 2 * c2];
        a1 += tv * W1[w * C1 + 2 * c2 + 1];
    }
    float dinv = 1.f / fmaxf(g_deg[n], 1.f);
    float xn = x[n];
    float h0 = fmaxf(a0 * dinv + xn * root1[2 * c2]     + b1[2 * c2],     0.f);
    float h1 = fmaxf(a1 * dinv + xn * root1[2 * c2 + 1] + b1[2 * c2 + 1], 0.f);
    __nv_bfloat162 hb = __float22bfloat162_rn(make_float2(h0, h1));
    g_h1b[t] = *(unsigned int*)&hb;
    if (c2 == 0) g_dinv[n] = dinv;
}

// ---------------- edge pass 2: 16 lanes/edge, 16B record + h1 gather ----------------
__global__ void k_edge2(int E) {
    int gt = blockIdx.x * blockDim.x + threadIdx.x;
    int lane = gt & 31;
    int warp = gt >> 5;
    int e = warp * 2 + (lane >> 4);
    int hl = lane & 15;
    if (e >= E) return;
    uint4 r = g_rec[e];
    int s   = (int)(r.x & 0xFFFFFu);
    int wi0 = (int)(r.x >> 20);
    int d   = (int)r.y;
    float2 bw01 = __bfloat1622float2(*(__nv_bfloat162*)&r.z);
    float2 bw23 = __bfloat1622float2(*(__nv_bfloat162*)&r.w);
    float2 h = __bfloat1622float2(*(__nv_bfloat162*)&g_h1b[s * 16 + hl]);
    unsigned int* base = g_Sb + d * 400 + wi0 * 16 + hl;
    {
        __nv_bfloat162 v = __float22bfloat162_rn(make_float2(bw01.x * h.x, bw01.x * h.y));
        red_bf162(base, *(unsigned int*)&v);
    }
    {
        __nv_bfloat162 v = __float22bfloat162_rn(make_float2(bw01.y * h.x, bw01.y * h.y));
        red_bf162(base + 16, *(unsigned int*)&v);
    }
    {
        __nv_bfloat162 v = __float22bfloat162_rn(make_float2(bw23.x * h.x, bw23.x * h.y));
        red_bf162(base + 80, *(unsigned int*)&v);
    }
    {
        __nv_bfloat162 v = __float22bfloat162_rn(make_float2(bw23.y * h.x, bw23.y * h.y));
        red_bf162(base + 96, *(unsigned int*)&v);
    }
}

// ---------------- fused GEMM (HMMA), M=128, 3-stage cp.async pipeline ----------------
__global__ void __launch_bounds__(256) k_gemm_mma(const float* __restrict__ b2,
                                                  const int* __restrict__ batch, int N) {
    __shared__ __align__(16) uint8_t smA[3][16384];
    int tid = threadIdx.x;
    int warp = tid >> 5, lane = tid & 31;
    int gid = lane >> 2, tig = lane & 3;
    int rowBase = blockIdx.x * 128;
    uint32_t smA_b = smem_u32(&smA[0][0]);

    int rowA[4], chA[4], stoff[4];
    bool inb[4];
#pragma unroll
    for (int j = 0; j < 4; j++) {
        int c = tid + 256 * j;
        rowA[j] = c >> 3; chA[j] = c & 7;
        stoff[j] = rowA[j] * 128 + ((chA[j] ^ (rowA[j] & 7)) << 4);
        inb[j] = (rowBase + rowA[j]) < N;
    }

    float acc[8][4];
#pragma unroll
    for (int g = 0; g < 8; g++)
#pragma unroll
        for (int j = 0; j < 4; j++) acc[g][j] = 0.f;

    int r0 = rowBase + warp * 16 + gid;
    int r1 = r0 + 8;

    // issue chunk c0 into buffer buf (cp.async, zero-fill for OOB/padding)
    auto issue = [&](int c0, int buf) {
        uint32_t sbase = smA_b + buf * 16384;
#pragma unroll
        for (int j = 0; j < 4; j++) {
            const void* src = (const void*)g_Sb;
            bool p = false;
            if (inb[j]) {
                if (c0 < 13) {
                    int off = c0 * 32 + chA[j] * 4;
                    if (off < 400) { src = (const void*)(g_Sb + (rowBase + rowA[j]) * 400 + off); p = true; }
                } else if (chA[j] < 4) {
                    src = (const void*)(g_h1b + (rowBase + rowA[j]) * 16 + chA[j] * 4);
                    p = true;
                }
            }
            cp_async16(sbase + stoff[j], src, p);
        }
        CP_COMMIT();
    };

    issue(0, 0);
    issue(1, 1);

#pragma unroll
    for (int c0 = 0; c0 < 14; c0++) {
        if (c0 < 13) { CP_WAIT(1); } else { CP_WAIT(0); }   // chunk c0 resident
        __syncthreads();                                     // all threads see it; prev buf free
        if (c0 + 2 < 14) issue(c0 + 2, (c0 + 2) % 3);
        uint32_t cbase = smA_b + (c0 % 3) * 16384;
#pragma unroll
        for (int ks = 0; ks < 4; ks++) {
            int mrow = warp * 16 + (lane & 15);
            uint32_t addr = cbase + mrow * 128 + (((ks * 2 + (lane >> 4)) ^ (mrow & 7)) << 4);
            uint32_t a0, a1, a2, a3;
            ldmatrix_x4(a0, a1, a2, a3, addr);
            int sg = c0 * 4 + ks;
            const uint2* bf = g_W2f + (sg << 8) + lane;
#pragma unroll
            for (int ng = 0; ng < 8; ng++) {
                uint2 b = bf[ng << 5];
                mma_bf16(acc[ng], a0, a1, a2, a3, b.x, b.y);
            }
        }
        if (c0 == 12) {
            float di0 = (r0 < N) ? g_dinv[r0] : 0.f;
            float di1 = (r1 < N) ? g_dinv[r1] : 0.f;
#pragma unroll
            for (int ng = 0; ng < 8; ng++) {
                acc[ng][0] *= di0; acc[ng][1] *= di0;
                acc[ng][2] *= di1; acc[ng][3] *= di1;
            }
        }
    }

    int bt0 = (r0 < N) ? batch[r0] : -1;
    int bt1 = (r1 < N) ? batch[r1] : -1;
#pragma unroll
    for (int ng = 0; ng < 8; ng++) {
        int col = ng * 8 + tig * 2;
        float2 bb = *(const float2*)(b2 + col);
        if (bt0 >= 0) {
            red_f32(g_pool + bt0 * C2 + col,     fmaxf(acc[ng][0] + bb.x, 0.f));
            red_f32(g_pool + bt0 * C2 + col + 1, fmaxf(acc[ng][1] + bb.y, 0.f));
        }
        if (bt1 >= 0) {
            red_f32(g_pool + bt1 * C2 + col,     fmaxf(acc[ng][2] + bb.x, 0.f));
            red_f32(g_pool + bt1 * C2 + col + 1, fmaxf(acc[ng][3] + bb.y, 0.f));
        }
    }

    // tail: zero T/deg for the next call (already consumed by h1 this call)
    int ztid = blockIdx.x * 256 + tid;
    int zstride = gridDim.x * 256;
    for (int i = ztid; i < N * K2; i += zstride) g_T[i] = 0.f;
    for (int i = ztid; i < N; i += zstride) g_deg[i] = 0.f;
}

// ---------------- head MLP + log_softmax + pool tail-zero ----------------
__global__ void k_mlp(const float* __restrict__ Wf1, const float* __restrict__ bf1,
                      const float* __restrict__ Wf2, const float* __restrict__ bf2,
                      const int* __restrict__ batch, int N,
                      float* __restrict__ out) {
    int b = blockIdx.x;
    int j = threadIdx.x;
    __shared__ float gs[C2];
    __shared__ float ts[128];
    __shared__ float lg[10];
    __shared__ float s_cinv;
    if (j == 0) {
        int lo = 0, hi = N;
        while (lo < hi) { int m = (lo + hi) >> 1; if (batch[m] < b) lo = m + 1; else hi = m; }
        int lo2 = lo; hi = N;
        while (lo2 < hi) { int m = (lo2 + hi) >> 1; if (batch[m] < b + 1) lo2 = m + 1; else hi = m; }
        s_cinv = 1.f / fmaxf((float)(lo2 - lo), 1.f);
    }
    __syncthreads();
    if (j < C2) gs[j] = g_pool[b * C2 + j] * s_cinv;
    __syncthreads();
    if (j < C2) g_pool[b * C2 + j] = 0.f;   // tail-zero for next call
    float t = bf1[j];
#pragma unroll
    for (int k = 0; k < C2; k++) t += gs[k] * Wf1[k * 128 + j];
    ts[j] = fmaxf(t, 0.f);
    __syncthreads();
    if (j < 10) {
        float a = bf2[j];
#pragma unroll
        for (int q = 0; q < 128; q++) a += ts[q] * Wf2[q * 10 + j];
        lg[j] = a;
    }
    __syncthreads();
    if (j == 0) {
        float m = lg[0];
#pragma unroll
        for (int q = 1; q < 10; q++) m = fmaxf(m, lg[q]);
        float s = 0.f;
#pragma unroll
        for (int q = 0; q < 10; q++) s += expf(lg[q] - m);
        float l = logf(s) + m;
#pragma unroll
        for (int q = 0; q < 10; q++) out[b * 10 + q] = lg[q] - l;
    }
}

// ---------------- launch ----------------
extern "C" void kernel_launch(void* const* d_in, const int* in_sizes, int n_in,
                              void* d_out, int out_size) {
    const float* x     = (const float*)d_in[0];
    const float* ea    = (const float*)d_in[1];
    const float* W1    = (const float*)d_in[2];
    const float* root1 = (const float*)d_in[3];
    const float* b1    = (const float*)d_in[4];
    const float* W2    = (const float*)d_in[5];
    const float* root2 = (const float*)d_in[6];
    const float* b2    = (const float*)d_in[7];
    const float* Wf1   = (const float*)d_in[8];
    const float* bf1   = (const float*)d_in[9];
    const float* Wf2   = (const float*)d_in[10];
    const float* bf2   = (const float*)d_in[11];
    const int*   ei    = (const int*)d_in[12];
    const int*   batch = (const int*)d_in[13];

    int N = in_sizes[0];
    int E = in_sizes[1] / 2;
    const int* src = ei;
    const int* dst = ei + E;
    float* out = (float*)d_out;

    k_edge1<<<ZB + (E + 255) / 256, 256>>>(x, ea, src, dst, W2, root2, E, N);
    k_h1<<<(N * 16 + 255) / 256, 256>>>(x, W1, root1, b1, N);
    k_edge2<<<(E * 16 + 255) / 256, 256>>>(E);
    k_gemm_mma<<<(N + 127) / 128, 256>>>(b2, batch, N);
    k_mlp<<<NG, 128>>>(Wf1, bf1, Wf2, bf2, batch, N, out);
}